// round 6
// baseline (speedup 1.0000x reference)
#include <cuda_runtime.h>

// DynamicGraphModule_15144054686343 — FINAL (R2 variant, measured best)
//
// Reference math reduces analytically:
//   scores[i,j] = row_term[i] + col_term[j] + b   (rank-1 + const)
//   adj = where(corr > 1.5, corr, 0)   -> elements in {0} U (1.5, inf)
//   adj = where(adj < -1.5, adj, 0)    -> identically ZERO (the two thresholds
//                                         are mutually exclusive)
//   out = adj @ (e @ W_gcn) + b_gcn    == broadcast(b_gcn) exactly
//                                         (fp32 0*x accumulates to 0.0 bitwise)
//
// Kernel: broadcast b_gcn [512] into out [1, 4096, 512] (8 MB fp32 stores).
//
// Convergence note (R0-R4 sweep): occupancy 17%-102%, 1-8 stores/thread,
// 128/256-bit STG, and TMA bulk-store all land within bench 6.62-6.88 us with
// nothing saturated (L2<=16%, issue<=17%, DRAM 0%). Duration is a fixed floor:
// ~0.7 us L2-write traffic + ~2.5 us launch/ramp + graph-replay constant.
// This shape (1024 blocks x 256 threads, depth-1 chain, 2 independent STG.128
// per thread, single wave) measured best on both ncu (4.77 us) and bench
// (6.624 us).

static constexpr int D_OUT_VEC4 = 128;          // 512 floats per row = 128 float4
static constexpr int TOTAL_VEC4 = 4096 * 128;   // 524288 float4 total
static constexpr int HALF_VEC4  = TOTAL_VEC4 / 2;

__global__ void __launch_bounds__(256)
broadcast_bias_kernel(const float4* __restrict__ bias4,
                      float4* __restrict__ out4)
{
    const int idx  = blockIdx.x * blockDim.x + threadIdx.x;  // 0..262143
    const float4 b = bias4[idx & (D_OUT_VEC4 - 1)];          // one L1/L2-broadcast load

    // Two independent, fully coalesced 128-bit stores (same column phase in
    // both halves since HALF_VEC4 is a multiple of 128).
    out4[idx]             = b;
    out4[idx + HALF_VEC4] = b;
}

extern "C" void kernel_launch(void* const* d_in, const int* in_sizes, int n_in,
                              void* d_out, int out_size)
{
    // metadata order:
    // 0 spans_embeddings, 1 W_c1, 2 b_c1, 3 W_c2, 4 b_c2,
    // 5 W_link, 6 b_link, 7 W_gcn, 8 b_gcn
    const float4* bias4 = (const float4*)d_in[8];
    float4* out4 = (float4*)d_out;
    (void)in_sizes; (void)n_in; (void)out_size;   // out_size = 4096*512 exactly

    broadcast_bias_kernel<<<HALF_VEC4 / 256, 256>>>(bias4, out4);
}

// round 7
// speedup vs baseline: 1.0386x; 1.0386x over previous
#include <cuda_runtime.h>

// DynamicGraphModule_15144054686343 — FINAL
//
// Reference math reduces analytically:
//   scores[i,j] = row_term[i] + col_term[j] + b   (rank-1 + const)
//   adj = where(corr > 1.5, corr, 0)   -> elements in {0} U (1.5, inf)
//   adj = where(adj < -1.5, adj, 0)    -> identically ZERO (the two thresholds
//                                         are mutually exclusive)
//   out = adj @ (e @ W_gcn) + b_gcn    == broadcast(b_gcn) exactly
//                                         (fp32 0*x accumulates to 0.0 bitwise)
//
// Kernel: broadcast b_gcn [512] into out [1, 4096, 512] (8 MB fp32 stores).
//
// Convergence note (R0-R5): six benches across occupancy 17-102%, 1-8
// stores/thread, STG.128 / STG.256 / TMA-bulk paths all land in
// bench 6.62-6.88 us; re-benching the SAME source moved 6.62 -> 6.88, so the
// whole spread is run-to-run noise. No pipe exceeds 16% in any profile.
// Duration = fixed floor: ~0.7 us L2-write traffic + ~2.5 us launch/ramp +
// graph-replay constant. Structural minimum reached (one wave, depth-1 chain,
// minimal traffic, one kernel). This is the simplest full-occupancy shape:
// 2048 blocks x 256 threads, one broadcast LDG + one coalesced STG.128 each.

static constexpr int D_OUT_VEC4 = 128;          // 512 floats per row = 128 float4
static constexpr int TOTAL_VEC4 = 4096 * 128;   // 524288 float4 = 8 MB

__global__ void __launch_bounds__(256)
broadcast_bias_kernel(const float4* __restrict__ bias4,
                      float4* __restrict__ out4)
{
    const int idx = blockIdx.x * blockDim.x + threadIdx.x;   // 0..524287
    // Column phase within a row; bias line is L2/L1-broadcast across all SMs.
    out4[idx] = bias4[idx & (D_OUT_VEC4 - 1)];
}

extern "C" void kernel_launch(void* const* d_in, const int* in_sizes, int n_in,
                              void* d_out, int out_size)
{
    // metadata order:
    // 0 spans_embeddings, 1 W_c1, 2 b_c1, 3 W_c2, 4 b_c2,
    // 5 W_link, 6 b_link, 7 W_gcn, 8 b_gcn
    const float4* bias4 = (const float4*)d_in[8];
    float4* out4 = (float4*)d_out;
    (void)in_sizes; (void)n_in; (void)out_size;   // out_size = 4096*512 exactly

    broadcast_bias_kernel<<<TOTAL_VEC4 / 256, 256>>>(bias4, out4);
}